// round 17
// baseline (speedup 1.0000x reference)
#include <cuda_runtime.h>
#include <math.h>

// Problem constants
#define BATCH 8
#define NNODES 4096
#define DIN0 64
#define DHID 128
#define DOUT0 64
#define CAP 512          // max neighbors per row (mean ~82 at 2% density; P(>512)~0)

#define LOG2E 1.4426950408889634f
#define NEGBIG (-1.0e30f)

// ---------------- static device scratch (no allocations allowed) -------------
// d_h1 aliasing: [0:2M) = y1 (layer1 score vecs) then h2 (layer2 linear out);
//                [2M:4M) = c (layer1 agg out).
__device__ int   d_col[NNODES * CAP + 16];       // pad: masked batch overread
__device__ int   d_deg[NNODES];
__device__ float d_h1[BATCH * NNODES * DHID];    // 16 MB, aliased as above
__device__ float d_g1[DIN0 * DIN0];              // G = W1^T W1 (64x64)

// ---------------- fused: build CSR (blocks 0..511) + G (512+) ---------------
__global__ void csr_prep_kernel(const float* __restrict__ graph,
                                const float* __restrict__ W1) {
    const unsigned FULL = 0xffffffffu;
    int blk = blockIdx.x;
    if (blk < NNODES / 8) {
        // ---- CSR build: warp per row, float4 scan ----
        int row  = blk * 8 + (threadIdx.x >> 5);
        int lane = threadIdx.x & 31;
        const float4* g = (const float4*)(graph + (size_t)row * NNODES);
        unsigned lt = (1u << lane) - 1u;
        int cnt = 0;
        int* outp = d_col + row * CAP;
#pragma unroll 2
        for (int base = 0; base < NNODES / 4; base += 32) {
            float4 v = g[base + lane];
            int col0 = (base + lane) * 4;
            unsigned b;
            b = __ballot_sync(FULL, v.x != 0.0f);
            if (v.x != 0.0f) { int p = cnt + __popc(b & lt); if (p < CAP) outp[p] = col0; }
            cnt += __popc(b);
            b = __ballot_sync(FULL, v.y != 0.0f);
            if (v.y != 0.0f) { int p = cnt + __popc(b & lt); if (p < CAP) outp[p] = col0 + 1; }
            cnt += __popc(b);
            b = __ballot_sync(FULL, v.z != 0.0f);
            if (v.z != 0.0f) { int p = cnt + __popc(b & lt); if (p < CAP) outp[p] = col0 + 2; }
            cnt += __popc(b);
            b = __ballot_sync(FULL, v.w != 0.0f);
            if (v.w != 0.0f) { int p = cnt + __popc(b & lt); if (p < CAP) outp[p] = col0 + 3; }
            cnt += __popc(b);
        }
        if (lane == 0) d_deg[row] = (cnt < CAP) ? cnt : CAP;
    } else {
        // ---- G[e][d] = sum_h W1[h][d] * W1[h][e] ----
        int i = (blk - NNODES / 8) * 256 + threadIdx.x;
        if (i < DIN0 * DIN0) {
            int d = i & 63, e = i >> 6;
            float s = 0.0f;
#pragma unroll 4
            for (int h = 0; h < DHID; h++)
                s = fmaf(W1[h * DIN0 + d], W1[h * DIN0 + e], s);
            d_g1[e * DIN0 + d] = s;
        }
    }
}

// ---------------- y1 = x @ G : G staged in smem, 32 rows/block ---------------
__global__ void y1_kernel(const float* __restrict__ x) {
    __shared__ float gs[DIN0 * DIN0];  // 16 KB
    __shared__ float xs[32 * DIN0];    // 8 KB
    int tid = threadIdx.x;
    long base = (long)blockIdx.x * 32;

    const float4* gg = (const float4*)d_g1;
    for (int i = tid; i < DIN0 * DIN0 / 4; i += 256) ((float4*)gs)[i] = gg[i];
    const float4* xg = (const float4*)(x + base * DIN0);
    for (int i = tid; i < 32 * DIN0 / 4; i += 256) ((float4*)xs)[i] = xg[i];
    __syncthreads();

    int c = tid & 63, rg = tid >> 6;   // rg 0..3 -> rows rg*8 .. rg*8+7
    int r0 = rg * 8;
    float acc[8];
#pragma unroll
    for (int r = 0; r < 8; r++) acc[r] = 0.0f;
    for (int k = 0; k < DIN0; k += 4) {
        float w0 = gs[(k + 0) * DIN0 + c];
        float w1 = gs[(k + 1) * DIN0 + c];
        float w2 = gs[(k + 2) * DIN0 + c];
        float w3 = gs[(k + 3) * DIN0 + c];
#pragma unroll
        for (int r = 0; r < 8; r++) {
            float4 xv = *(const float4*)&xs[(r0 + r) * DIN0 + k];
            acc[r] = fmaf(xv.x, w0, fmaf(xv.y, w1, fmaf(xv.z, w2, fmaf(xv.w, w3, acc[r]))));
        }
    }
#pragma unroll
    for (int r = 0; r < 8; r++) d_h1[(base + r0 + r) * DIN0 + c] = acc[r];
}

// ---------------- fused MLP: h2 = relu(c @ W1^T + b1) @ W2^T -----------------
// 16 rows/block, 256 threads. Weights read in ORIGINAL row-major layout via
// LDG.128 (thread-per-out-col => W[c][k..k+3] contiguous). Phase A: 2 cols per
// thread so x LDS loads are shared. FMA chains keep the k-major 4-wide order.
__global__ void mlp_kernel(const float* __restrict__ W1, const float* __restrict__ b1,
                           const float* __restrict__ W2) {
    __shared__ float xs[16 * DIN0];    // 4 KB: staged c rows
    __shared__ float st[16 * DHID];    // 8 KB: t1 rows
    const float* cbase = d_h1 + (size_t)BATCH * NNODES * DIN0;
    long base = (long)blockIdx.x * 16;
    int tid = threadIdx.x;

    const float4* xg = (const float4*)(cbase + base * DIN0);
    ((float4*)xs)[tid] = xg[tid];      // 256 float4 = 16*64 floats
    __syncthreads();

    // phase A: t1[r][c] = relu(sum_k c[r][k] W1[c][k] + b1[c]); 2 cols/thread
    {
        int ca = tid & 63, cb = ca + 64;
        int r0 = (tid >> 6) << 2;      // 4 rows per thread
        float bA = b1[ca], bB = b1[cb];
        float accA[4], accB[4];
#pragma unroll
        for (int r = 0; r < 4; r++) { accA[r] = 0.0f; accB[r] = 0.0f; }
        for (int k = 0; k < DIN0; k += 4) {
            float4 wA = *(const float4*)&W1[ca * DIN0 + k];
            float4 wB = *(const float4*)&W1[cb * DIN0 + k];
#pragma unroll
            for (int r = 0; r < 4; r++) {
                float4 xv = *(const float4*)&xs[(r0 + r) * DIN0 + k];
                accA[r] = fmaf(xv.x, wA.x, fmaf(xv.y, wA.y, fmaf(xv.z, wA.z, fmaf(xv.w, wA.w, accA[r]))));
                accB[r] = fmaf(xv.x, wB.x, fmaf(xv.y, wB.y, fmaf(xv.z, wB.z, fmaf(xv.w, wB.w, accB[r]))));
            }
        }
#pragma unroll
        for (int r = 0; r < 4; r++) {
            st[(r0 + r) * DHID + ca] = fmaxf(accA[r] + bA, 0.0f);
            st[(r0 + r) * DHID + cb] = fmaxf(accB[r] + bB, 0.0f);
        }
    }
    __syncthreads();

    // phase B: h2[r][c2] = sum_k t1[r][k] W2[c2][k]; 1 col x 4 rows per thread
    {
        int c2 = tid & 63;
        int r0 = (tid >> 6) << 2;
        float o[4];
#pragma unroll
        for (int r = 0; r < 4; r++) o[r] = 0.0f;
        for (int k = 0; k < DHID; k += 4) {
            float4 w = *(const float4*)&W2[c2 * DHID + k];
#pragma unroll
            for (int r = 0; r < 4; r++) {
                float4 xv = *(const float4*)&st[(r0 + r) * DHID + k];
                o[r] = fmaf(xv.x, w.x, fmaf(xv.y, w.y, fmaf(xv.z, w.z, fmaf(xv.w, w.w, o[r]))));
            }
        }
#pragma unroll
        for (int r = 0; r < 4; r++)
            d_h1[(base + r0 + r) * DOUT0 + c2] = o[r];
    }
}

// ---------------- sparse GAT aggregation (D=64): 2x16-lane engines (R12) -----
template <bool HAS_BIAS>
__device__ __forceinline__ void agg_body64(const float* __restrict__ fsrc,
                                           const float* __restrict__ gsrc,
                                           const float* __restrict__ bias,
                                           float* __restrict__ out) {
    const unsigned FULL = 0xffffffffu;
    int warp  = threadIdx.x >> 5;
    int lane  = threadIdx.x & 31;
    int k16   = lane & 15;
    int grp   = lane >> 4;
    int gbase = grp << 4;

    int row = blockIdx.x * 8 + warp;                 // grid exact: B*N/8 blocks
    int n = row & (NNODES - 1);
    const float* hb = gsrc + ((size_t)(row - n) << 6);
    unsigned loff = (unsigned)k16 << 2;              // 4 dims per lane

    float4 ft = *(const float4*)(fsrc + ((size_t)row << 6) + loff);
    float f0 = ft.x * LOG2E, f1 = ft.y * LOG2E;
    float f2 = ft.z * LOG2E, f3 = ft.w * LOG2E;

    float M = NEGBIG, Z = 0.0f;
    float a0 = 0.f, a1 = 0.f, a2 = 0.f, a3 = 0.f;
    int deg = d_deg[n];
    const int* cols = d_col + n * CAP;

    // subgroup (k16>>2) -> neighbor slot j: 0->0, 1->2, 2->1, 3->3
    int sub  = k16 >> 2;
    int jmap = ((sub & 1) << 1) | (sub >> 1);
    int thr  = deg - (grp << 2) - jmap;              // slot valid iff i < thr

    for (int i = 0; i < deg; i += 8) {
        int4 c4 = *(const int4*)(cols + i + (grp << 2));
        float4 g0 = *(const float4*)(hb + (((unsigned)c4.x << 6) + loff));
        float4 g1 = *(const float4*)(hb + (((unsigned)c4.y << 6) + loff));
        float4 g2 = *(const float4*)(hb + (((unsigned)c4.z << 6) + loff));
        float4 g3 = *(const float4*)(hb + (((unsigned)c4.w << 6) + loff));

        float p0 = fmaf(f0, g0.x, fmaf(f1, g0.y, fmaf(f2, g0.z, f3 * g0.w)));
        float p1 = fmaf(f0, g1.x, fmaf(f1, g1.y, fmaf(f2, g1.z, f3 * g1.w)));
        float p2 = fmaf(f0, g2.x, fmaf(f1, g2.y, fmaf(f2, g2.z, f3 * g2.w)));
        float p3 = fmaf(f0, g3.x, fmaf(f1, g3.y, fmaf(f2, g3.z, f3 * g3.w)));

        // merged 4-way reduction within the 16-lane group (5 SHFLs)
        float sA = (k16 & 8) ? p1 : p0, tA = (k16 & 8) ? p0 : p1;
        sA += __shfl_xor_sync(FULL, tA, 8);
        float sB = (k16 & 8) ? p3 : p2, tB = (k16 & 8) ? p2 : p3;
        sB += __shfl_xor_sync(FULL, tB, 8);
        float u  = (k16 & 4) ? sB : sA, ut = (k16 & 4) ? sA : sB;
        u += __shfl_xor_sync(FULL, ut, 4);
        u += __shfl_xor_sync(FULL, u, 2);
        u += __shfl_xor_sync(FULL, u, 1);
        // subgroup holds: base0=d0, base4=d2, base8=d1, base12=d3

        u = (i < thr) ? u : -INFINITY;               // mask invalid slots

        // group max (2 SHFLs)
        float bm = fmaxf(u, __shfl_xor_sync(FULL, u, 4));
        bm = fmaxf(bm, __shfl_xor_sync(FULL, bm, 8));

        if (bm > M) {                                // rare after warmup
            float sc = exp2f(M - bm);
            Z *= sc; a0 *= sc; a1 *= sc; a2 *= sc; a3 *= sc;
            M = bm;
        }
        float w = exp2f(u - M);                      // ONE exp2 for 4 scores

        // Z += sum of the group's 4 weights (2 SHFLs)
        float zs = w + __shfl_xor_sync(FULL, w, 4);
        zs += __shfl_xor_sync(FULL, zs, 8);
        Z += zs;

        // broadcast weights to all group lanes (4 SHFLs)
        float w0 = __shfl_sync(FULL, w, gbase + 0);
        float w1 = __shfl_sync(FULL, w, gbase + 8);
        float w2 = __shfl_sync(FULL, w, gbase + 4);
        float w3 = __shfl_sync(FULL, w, gbase + 12);

        a0 = fmaf(w0, g0.x, a0); a1 = fmaf(w0, g0.y, a1);
        a2 = fmaf(w0, g0.z, a2); a3 = fmaf(w0, g0.w, a3);
        a0 = fmaf(w1, g1.x, a0); a1 = fmaf(w1, g1.y, a1);
        a2 = fmaf(w1, g1.z, a2); a3 = fmaf(w1, g1.w, a3);
        a0 = fmaf(w2, g2.x, a0); a1 = fmaf(w2, g2.y, a1);
        a2 = fmaf(w2, g2.z, a2); a3 = fmaf(w2, g2.w, a3);
        a0 = fmaf(w3, g3.x, a0); a1 = fmaf(w3, g3.y, a1);
        a2 = fmaf(w3, g3.z, a2); a3 = fmaf(w3, g3.w, a3);
    }

    // ---- merge the two groups (flash combine) ----
    float Mo   = __shfl_xor_sync(FULL, M, 16);
    float newM = fmaxf(M, Mo);
    float scl  = exp2f(M - newM);                    // empty group: 0
    Z *= scl; a0 *= scl; a1 *= scl; a2 *= scl; a3 *= scl;
    float Zt = Z + __shfl_xor_sync(FULL, Z, 16);
    float b0 = a0 + __shfl_xor_sync(FULL, a0, 16);
    float b1v = a1 + __shfl_xor_sync(FULL, a1, 16);
    float b2 = a2 + __shfl_xor_sync(FULL, a2, 16);
    float b3 = a3 + __shfl_xor_sync(FULL, a3, 16);

    float inv = 1.0f / Zt;                           // Zt >= 1 (max weight = 1)
    float o0 = b0 * inv, o1 = b1v * inv, o2 = b2 * inv, o3 = b3 * inv;
    if (HAS_BIAS) {
        o0 += bias[loff]; o1 += bias[loff + 1];
        o2 += bias[loff + 2]; o3 += bias[loff + 3];
    }
    if (grp == 0)
        *(float4*)(out + ((size_t)row << 6) + loff) = make_float4(o0, o1, o2, o3);
}

__global__ void agg1_kernel(const float* __restrict__ x) {
    // scores via y1 = x G (fsrc = d_h1[0:2M)); values = x; out = c (d_h1[2M:4M))
    agg_body64<false>(d_h1, x, nullptr, d_h1 + (size_t)BATCH * NNODES * DIN0);
}
__global__ void agg2_kernel(const float* __restrict__ b2, float* __restrict__ out) {
    // scores and values both h2 (d_h1[0:2M), written by mlp_kernel)
    agg_body64<true>(d_h1, d_h1, b2, out);
}

// ---------------- launch ------------------------------------------------------
extern "C" void kernel_launch(void* const* d_in, const int* in_sizes, int n_in,
                              void* d_out, int out_size) {
    const float* flow_x = (const float*)d_in[0];   // [B,N,64]
    const float* graph  = (const float*)d_in[1];   // [N,N]
    const float* W1     = (const float*)d_in[2];   // [128,64]
    const float* b1     = (const float*)d_in[3];   // [128]
    const float* W2     = (const float*)d_in[4];   // [64,128]
    const float* b2     = (const float*)d_in[5];   // [64]
    float*       outp   = (float*)d_out;           // [B,N,1,64]

    // 1) CSR build (blocks 0..511) + G (blocks 512..527), fused
    csr_prep_kernel<<<NNODES / 8 + 16, 256>>>(graph, W1);
    // 2) y1 = x @ G  (64-dim score vectors for layer 1)
    y1_kernel<<<BATCH * NNODES / 32, 256>>>(flow_x);
    // 3) layer-1 sparse attention in input space: c = softmax(y1.x) @ x
    agg1_kernel<<<(BATCH * NNODES) / 8, 256>>>(flow_x);
    // 4) fused MLP: h2 = relu(c @ W1^T + b1) @ W2^T
    mlp_kernel<<<BATCH * NNODES / 16, 256>>>(W1, b1, W2);
    // 5) layer-2 sparse attention + bias -> final output
    agg2_kernel<<<(BATCH * NNODES) / 8, 256>>>(b2, outp);
}